// round 1
// baseline (speedup 1.0000x reference)
#include <cuda_runtime.h>
#include <math.h>
#include <stdint.h>

// ---------------- problem constants ----------------
static constexpr int   N_  = 50000;
static constexpr int   E_  = 200000;
static constexpr int   H_  = 256;
static constexpr int   T_  = 16;
static constexpr int   FE_ = 64;
static constexpr int   O_  = 64;

// ---------------- scratch (device globals; no allocation allowed) ----------------
__device__ float g_X   [(size_t)N_ * 256];   // packed [node_feat | memory]
__device__ float g_h   [(size_t)N_ * 256];   // node hidden state
__device__ float g_hkvq[(size_t)N_ * 768];   // [HK | HV | HQ] per node
__device__ float g_msge[(size_t)E_ * 80];    // [edge_feat | tenc] per edge
__device__ float g_ekv [(size_t)E_ * 512];   // [EK | EV] per edge
__device__ float g_agg [(size_t)N_ * 256];   // attention aggregate
__device__ float g_nrm [N_];                 // attention normalizer
__device__ float g_Wh  [2 * 768 * 256];      // packed per-layer node weights
__device__ float g_We  [2 * 512 * 80];       // packed per-layer edge weights
__device__ float g_b   [2 * 768];            // packed [bk | bv | bq_eff]

// ---------------- pack kernels ----------------
__global__ void pack_x_kernel(const float* __restrict__ nf, const float* __restrict__ mem) {
    int idx = blockIdx.x * blockDim.x + threadIdx.x;
    int stride = gridDim.x * blockDim.x;
    for (int i = idx; i < N_ * 256; i += stride) {
        int n = i >> 8, j = i & 255;
        g_X[i] = (j < 128) ? nf[n * 128 + j] : mem[n * 128 + (j - 128)];
    }
}

__global__ void pack_weights_kernel(const float* __restrict__ wk_w, const float* __restrict__ wk_b,
                                    const float* __restrict__ wv_w, const float* __restrict__ wv_b,
                                    const float* __restrict__ wq_w, const float* __restrict__ wq_b,
                                    const float* __restrict__ te_phi) {
    int idx = blockIdx.x * blockDim.x + threadIdx.x;
    int stride = gridDim.x * blockDim.x;
    // node-path weights: [wk[:, :256]; wv[:, :256]; wq[:, :256]] -> (768, 256) per layer
    for (int i = idx; i < 2 * 768 * 256; i += stride) {
        int l = i / (768 * 256); int r = (i / 256) % 768; int k = i & 255;
        float v;
        if (r < 256)      v = wk_w[(size_t)(l * 256 + r)       * 336 + k];
        else if (r < 512) v = wv_w[(size_t)(l * 256 + (r-256)) * 336 + k];
        else              v = wq_w[(size_t)(l * 256 + (r-512)) * 272 + k];
        g_Wh[i] = v;
    }
    // edge-path weights: [wk[:, 256:336]; wv[:, 256:336]] -> (512, 80) per layer
    for (int i = idx; i < 2 * 512 * 80; i += stride) {
        int l = i / (512 * 80); int r = (i / 80) % 512; int k = i % 80;
        float v;
        if (r < 256) v = wk_w[(size_t)(l * 256 + r)       * 336 + 256 + k];
        else         v = wv_w[(size_t)(l * 256 + (r-256)) * 336 + 256 + k];
        g_We[i] = v;
    }
    // biases; bq folds in the (constant) query time-encoding contribution
    for (int i = idx; i < 2 * 768; i += stride) {
        int l = i / 768; int r = i % 768;
        float v;
        if (r < 256)      v = wk_b[l * 256 + r];
        else if (r < 512) v = wv_b[l * 256 + (r - 256)];
        else {
            int rq = r - 512;
            v = wq_b[l * 256 + rq];
            for (int t = 0; t < 16; t++) {
                float ph = te_phi[l * 16 + t];
                float qt = (t == 0) ? ph : sinf(ph);
                v += wq_w[(size_t)(l * 256 + rq) * 272 + 256 + t] * qt;
            }
        }
        g_b[i] = v;
    }
}

// build [edge_feat | tenc_l] per edge
__global__ void build_msge_kernel(const float* __restrict__ ef, const float* __restrict__ et,
                                  const float* __restrict__ te_w, const float* __restrict__ te_phi, int l) {
    int idx = blockIdx.x * blockDim.x + threadIdx.x;
    int stride = gridDim.x * blockDim.x;
    for (int i = idx; i < E_ * 80; i += stride) {
        int e = i / 80, j = i % 80;
        float v;
        if (j < 64) {
            v = ef[(size_t)e * 64 + j];
        } else {
            int t = j - 64;
            float td = -et[e];
            float wt = td * te_w[l * 16 + t] + te_phi[l * 16 + t];
            v = (t == 0) ? wt : sinf(wt);
        }
        g_msge[i] = v;
    }
}

__global__ void zero_agg_kernel() {
    int idx = blockIdx.x * blockDim.x + threadIdx.x;
    if (idx < N_ * 64) reinterpret_cast<float4*>(g_agg)[idx] = make_float4(0.f, 0.f, 0.f, 0.f);
    if (idx < N_) g_nrm[idx] = 0.f;
}

// ---------------- generic fp32 tiled GEMM: C = A(MxK) @ W(NoutxK)^T (+bias) (+gelu) ----------------
template <bool GELU>
__global__ __launch_bounds__(256)
void gemm_kernel(const float* __restrict__ A, const float* __restrict__ W,
                 const float* __restrict__ bias, float* __restrict__ C,
                 int M, int Nout, int K) {
    __shared__ __align__(16) float As[16][68];
    __shared__ __align__(16) float Bs[16][68];
    int t  = threadIdx.x;
    int bm = blockIdx.x * 64, bn = blockIdx.y * 64;
    int tx = t & 15, ty = t >> 4;
    int lrow = t >> 2, lc = (t & 3) * 4;
    float acc[4][4] = {};
    for (int k0 = 0; k0 < K; k0 += 16) {
        int ar = bm + lrow;
        float4 av = make_float4(0.f, 0.f, 0.f, 0.f);
        if (ar < M) av = *reinterpret_cast<const float4*>(A + (size_t)ar * K + k0 + lc);
        As[lc + 0][lrow] = av.x; As[lc + 1][lrow] = av.y;
        As[lc + 2][lrow] = av.z; As[lc + 3][lrow] = av.w;
        float4 bv = *reinterpret_cast<const float4*>(W + (size_t)(bn + lrow) * K + k0 + lc);
        Bs[lc + 0][lrow] = bv.x; Bs[lc + 1][lrow] = bv.y;
        Bs[lc + 2][lrow] = bv.z; Bs[lc + 3][lrow] = bv.w;
        __syncthreads();
#pragma unroll
        for (int kk = 0; kk < 16; kk++) {
            float4 a4 = *reinterpret_cast<const float4*>(&As[kk][ty * 4]);
            float4 b4 = *reinterpret_cast<const float4*>(&Bs[kk][tx * 4]);
            float a_[4] = {a4.x, a4.y, a4.z, a4.w};
            float b_[4] = {b4.x, b4.y, b4.z, b4.w};
#pragma unroll
            for (int i = 0; i < 4; i++)
#pragma unroll
                for (int j = 0; j < 4; j++)
                    acc[i][j] = fmaf(a_[i], b_[j], acc[i][j]);
        }
        __syncthreads();
    }
#pragma unroll
    for (int i = 0; i < 4; i++) {
        int row = bm + ty * 4 + i;
        if (row >= M) continue;
#pragma unroll
        for (int j = 0; j < 4; j++) {
            int col = bn + tx * 4 + j;
            float v = acc[i][j] + (bias ? bias[col] : 0.f);
            if (GELU) v = 0.5f * v * (1.0f + erff(v * 0.70710678118654752f));
            C[(size_t)row * Nout + col] = v;
        }
    }
}

// ---------------- per-edge attention + scatter ----------------
__device__ __forceinline__ void red_add4(float* p, float a, float b, float c, float d) {
    asm volatile("red.global.add.v4.f32 [%0], {%1, %2, %3, %4};"
                 :: "l"(p), "f"(a), "f"(b), "f"(c), "f"(d) : "memory");
}

__global__ __launch_bounds__(256)
void edge_attn_kernel(const int* __restrict__ src, const int* __restrict__ dst, int l) {
    int gw = (blockIdx.x * blockDim.x + threadIdx.x) >> 5;
    int lane = threadIdx.x & 31;
    if (gw >= E_) return;
    int e = gw;
    int s = src[e], d = dst[e];
    int jn = dst[d];                 // faithful h_dst[dst] quirk: node dst[dst[e]]
    const float* bb = g_b + l * 768;
    size_t sb = (size_t)s  * 768;
    size_t jb = (size_t)jn * 768;
    size_t eb = (size_t)e  * 512;
    int o = lane * 8;

    // K = HK[s] + EK[e] + bk ; Q = HQ[j] + bq_eff ; dot over this lane's 8 dims (one head per 8 lanes)
    float acc = 0.f;
#pragma unroll
    for (int i = 0; i < 8; i += 4) {
        float4 hk = *reinterpret_cast<const float4*>(g_hkvq + sb + o + i);
        float4 ek = *reinterpret_cast<const float4*>(g_ekv + eb + o + i);
        float4 bk = *reinterpret_cast<const float4*>(bb + o + i);
        float4 hq = *reinterpret_cast<const float4*>(g_hkvq + jb + 512 + o + i);
        float4 bq = *reinterpret_cast<const float4*>(bb + 512 + o + i);
        float kx = hk.x + ek.x + bk.x, ky = hk.y + ek.y + bk.y;
        float kz = hk.z + ek.z + bk.z, kw = hk.w + ek.w + bk.w;
        float qx = hq.x + bq.x, qy = hq.y + bq.y, qz = hq.z + bq.z, qw = hq.w + bq.w;
        acc += kx * qx + ky * qy + kz * qz + kw * qw;
    }
    // reduce within each head (8 lanes)
    acc += __shfl_xor_sync(0xffffffffu, acc, 1);
    acc += __shfl_xor_sync(0xffffffffu, acc, 2);
    acc += __shfl_xor_sync(0xffffffffu, acc, 4);
    float sc = acc * 0.125f;                      // / sqrt(64)
    sc = fminf(5.0f, fmaxf(-5.0f, sc));
    float a = expf(sc);
    // mean over 4 heads
    float sm = a;
    sm += __shfl_xor_sync(0xffffffffu, sm, 8);
    sm += __shfl_xor_sync(0xffffffffu, sm, 16);
    float af = sm * 0.25f;

    // V = HV[s] + EV[e] + bv ; scatter V*af
    float v[8];
#pragma unroll
    for (int i = 0; i < 8; i += 4) {
        float4 hv = *reinterpret_cast<const float4*>(g_hkvq + sb + 256 + o + i);
        float4 ev = *reinterpret_cast<const float4*>(g_ekv + eb + 256 + o + i);
        float4 bv = *reinterpret_cast<const float4*>(bb + 256 + o + i);
        v[i + 0] = (hv.x + ev.x + bv.x) * af;
        v[i + 1] = (hv.y + ev.y + bv.y) * af;
        v[i + 2] = (hv.z + ev.z + bv.z) * af;
        v[i + 3] = (hv.w + ev.w + bv.w) * af;
    }
    float* ag = g_agg + (size_t)d * 256 + o;
    red_add4(ag,     v[0], v[1], v[2], v[3]);
    red_add4(ag + 4, v[4], v[5], v[6], v[7]);
    if (lane == 0) atomicAdd(g_nrm + d, af);
}

// ---------------- node update: h = LN(h + LN(agg/(nrm+1e-8))) ----------------
__global__ __launch_bounds__(256)
void node_update_kernel(const float* __restrict__ aw, const float* __restrict__ ab,
                        const float* __restrict__ lw, const float* __restrict__ lb) {
    int gw = (blockIdx.x * blockDim.x + threadIdx.x) >> 5;
    int lane = threadIdx.x & 31;
    if (gw >= N_) return;
    size_t base = (size_t)gw * 256;
    int o = lane * 8;
    float inv = 1.0f / (g_nrm[gw] + 1e-8f);
    float x[8];
    {
        float4 x0 = *reinterpret_cast<const float4*>(g_agg + base + o);
        float4 x1 = *reinterpret_cast<const float4*>(g_agg + base + o + 4);
        x[0] = x0.x * inv; x[1] = x0.y * inv; x[2] = x0.z * inv; x[3] = x0.w * inv;
        x[4] = x1.x * inv; x[5] = x1.y * inv; x[6] = x1.z * inv; x[7] = x1.w * inv;
    }
    // LN1
    float s = 0.f;
#pragma unroll
    for (int i = 0; i < 8; i++) s += x[i];
#pragma unroll
    for (int m = 16; m >= 1; m >>= 1) s += __shfl_xor_sync(0xffffffffu, s, m);
    float mean = s * (1.0f / 256.0f);
    float vv = 0.f;
#pragma unroll
    for (int i = 0; i < 8; i++) { float dxx = x[i] - mean; vv += dxx * dxx; }
#pragma unroll
    for (int m = 16; m >= 1; m >>= 1) vv += __shfl_xor_sync(0xffffffffu, vv, m);
    float is = rsqrtf(vv * (1.0f / 256.0f) + 1e-5f);
    float r[8];
#pragma unroll
    for (int i = 0; i < 8; i++) {
        float hn = (x[i] - mean) * is * aw[o + i] + ab[o + i];
        r[i] = g_h[base + o + i] + hn;
    }
    // LN2
    float s2 = 0.f;
#pragma unroll
    for (int i = 0; i < 8; i++) s2 += r[i];
#pragma unroll
    for (int m = 16; m >= 1; m >>= 1) s2 += __shfl_xor_sync(0xffffffffu, s2, m);
    float mean2 = s2 * (1.0f / 256.0f);
    float v2 = 0.f;
#pragma unroll
    for (int i = 0; i < 8; i++) { float dxx = r[i] - mean2; v2 += dxx * dxx; }
#pragma unroll
    for (int m = 16; m >= 1; m >>= 1) v2 += __shfl_xor_sync(0xffffffffu, v2, m);
    float is2 = rsqrtf(v2 * (1.0f / 256.0f) + 1e-5f);
#pragma unroll
    for (int i = 0; i < 8; i++)
        g_h[base + o + i] = (r[i] - mean2) * is2 * lw[o + i] + lb[o + i];
}

// ---------------- launch ----------------
extern "C" void kernel_launch(void* const* d_in, const int* in_sizes, int n_in,
                              void* d_out, int out_size) {
    const float* node_feat  = (const float*)d_in[0];
    const float* memory     = (const float*)d_in[1];
    const int*   eidx       = (const int*)  d_in[2];
    const float* edge_feat  = (const float*)d_in[3];
    const float* edge_times = (const float*)d_in[4];
    const float* in_w       = (const float*)d_in[5];
    const float* in_b       = (const float*)d_in[6];
    const float* te_w       = (const float*)d_in[7];
    const float* te_phi     = (const float*)d_in[8];
    const float* wq_w       = (const float*)d_in[9];
    const float* wq_b       = (const float*)d_in[10];
    const float* wk_w       = (const float*)d_in[11];
    const float* wk_b       = (const float*)d_in[12];
    const float* wv_w       = (const float*)d_in[13];
    const float* wv_b       = (const float*)d_in[14];
    const float* attn_ln_w  = (const float*)d_in[15];
    const float* attn_ln_b  = (const float*)d_in[16];
    const float* ln_w       = (const float*)d_in[17];
    const float* ln_b       = (const float*)d_in[18];
    const float* out_w      = (const float*)d_in[19];
    const float* out_b      = (const float*)d_in[20];
    const int* src = eidx;
    const int* dst = eidx + E_;
    float* out = (float*)d_out;

    float *pX, *ph, *phkvq, *pmsge, *pekv, *pWh, *pWe;
    cudaGetSymbolAddress((void**)&pX,    g_X);
    cudaGetSymbolAddress((void**)&ph,    g_h);
    cudaGetSymbolAddress((void**)&phkvq, g_hkvq);
    cudaGetSymbolAddress((void**)&pmsge, g_msge);
    cudaGetSymbolAddress((void**)&pekv,  g_ekv);
    cudaGetSymbolAddress((void**)&pWh,   g_Wh);
    cudaGetSymbolAddress((void**)&pWe,   g_We);

    pack_x_kernel<<<4096, 256>>>(node_feat, memory);
    pack_weights_kernel<<<1024, 256>>>(wk_w, wk_b, wv_w, wv_b, wq_w, wq_b, te_phi);

    // h = [node_feat|memory] @ in_w^T + in_b
    gemm_kernel<false><<<dim3(782, 4), 256>>>(pX, in_w, in_b, ph, N_, 256, 256);

    for (int l = 0; l < 2; l++) {
        build_msge_kernel<<<16384, 256>>>(edge_feat, edge_times, te_w, te_phi, l);
        // EKV = [ef|tenc] @ We^T   (E x 512, K=80)
        gemm_kernel<false><<<dim3(3125, 8), 256>>>(pmsge, pWe + (size_t)l * 512 * 80,
                                                   nullptr, pekv, E_, 512, 80);
        // HKVQ = h @ Wh^T          (N x 768, K=256)
        gemm_kernel<false><<<dim3(782, 12), 256>>>(ph, pWh + (size_t)l * 768 * 256,
                                                   nullptr, phkvq, N_, 768, 256);
        zero_agg_kernel<<<12500, 256>>>();
        edge_attn_kernel<<<25000, 256>>>(src, dst, l);
        node_update_kernel<<<6250, 256>>>(attn_ln_w + l * 256, attn_ln_b + l * 256,
                                          ln_w + l * 256, ln_b + l * 256);
    }

    // out = gelu(h @ out_w^T + out_b)
    gemm_kernel<true><<<dim3(782, 1), 256>>>(ph, out_w, out_b, out, N_, O_, 256);
}

// round 2
// speedup vs baseline: 1.4121x; 1.4121x over previous
#include <cuda_runtime.h>
#include <math.h>
#include <stdint.h>

// ---------------- problem constants ----------------
static constexpr int N_  = 50000;
static constexpr int E_  = 200000;

// ---------------- scratch (device globals) ----------------
__device__ float g_X   [(size_t)N_ * 256];   // packed [node_feat | memory]
__device__ float g_h   [(size_t)N_ * 256];   // node hidden state
__device__ float g_hkvq[(size_t)N_ * 768];   // [HK | HV | HQ] per node
__device__ float g_msge[(size_t)E_ * 80];    // [edge_feat | tenc] per edge
__device__ float g_P   [(size_t)N_ * 320];   // per-head We_k^T @ (HQ + bq): 4 x 80
__device__ float g_agg [(size_t)N_ * 256];   // sum af*(HV[src]+bv)
__device__ float g_agg2[(size_t)N_ * 256];   // We_v @ aggm
__device__ float g_aggm[(size_t)N_ * 80];    // sum af*msg
__device__ float g_nrm [N_];
__device__ float g_Wh  [2 * 768 * 256];      // [Wk_h; Wv_h; Wq_h] per layer
__device__ float g_WeTk[2 * 80 * 256];       // We_k^T  (80 x 256) per layer
__device__ float g_Wev [2 * 256 * 80];       // We_v    (256 x 80) per layer
__device__ float g_b   [2 * 768];            // [bk | bv | bq_eff]
__device__ float g_cb  [2 * 320];            // per-head We_k^T @ bq_eff

// ---------------- f32x2 helpers ----------------
__device__ __forceinline__ unsigned long long pk2(float x) {
    unsigned long long r;
    asm("mov.b64 %0, {%1, %1};" : "=l"(r) : "f"(x));
    return r;
}
__device__ __forceinline__ unsigned long long ffma2(unsigned long long a,
                                                    unsigned long long b,
                                                    unsigned long long c) {
    unsigned long long d;
    asm("fma.rn.f32x2 %0, %1, %2, %3;" : "=l"(d) : "l"(a), "l"(b), "l"(c));
    return d;
}
__device__ __forceinline__ float2 up2(unsigned long long v) {
    float2 f;
    asm("mov.b64 {%0, %1}, %2;" : "=f"(f.x), "=f"(f.y) : "l"(v));
    return f;
}

// ---------------- pack kernels ----------------
__global__ void pack_x_kernel(const float* __restrict__ nf, const float* __restrict__ mem) {
    int idx = blockIdx.x * blockDim.x + threadIdx.x;
    int stride = gridDim.x * blockDim.x;
    for (int i = idx; i < N_ * 256; i += stride) {
        int n = i >> 8, j = i & 255;
        g_X[i] = (j < 128) ? nf[n * 128 + j] : mem[n * 128 + (j - 128)];
    }
}

__global__ void pack_weights_kernel(const float* __restrict__ wk_w, const float* __restrict__ wk_b,
                                    const float* __restrict__ wv_w, const float* __restrict__ wv_b,
                                    const float* __restrict__ wq_w, const float* __restrict__ wq_b,
                                    const float* __restrict__ te_phi) {
    int idx = blockIdx.x * blockDim.x + threadIdx.x;
    int stride = gridDim.x * blockDim.x;
    // node-path weights: [wk[:, :256]; wv[:, :256]; wq[:, :256]] -> (768, 256) per layer
    for (int i = idx; i < 2 * 768 * 256; i += stride) {
        int l = i / (768 * 256); int r = (i / 256) % 768; int k = i & 255;
        float v;
        if (r < 256)      v = wk_w[(size_t)(l * 256 + r)       * 336 + k];
        else if (r < 512) v = wv_w[(size_t)(l * 256 + (r-256)) * 336 + k];
        else              v = wq_w[(size_t)(l * 256 + (r-512)) * 272 + k];
        g_Wh[i] = v;
    }
    // We_k^T: (80 x 256): [p][r] = wk_w[r][256+p]
    for (int i = idx; i < 2 * 80 * 256; i += stride) {
        int l = i / (80 * 256); int p = (i / 256) % 80; int r = i & 255;
        g_WeTk[i] = wk_w[(size_t)(l * 256 + r) * 336 + 256 + p];
    }
    // We_v: (256 x 80): [r][p] = wv_w[r][256+p]
    for (int i = idx; i < 2 * 256 * 80; i += stride) {
        int l = i / (256 * 80); int r = (i / 80) % 256; int p = i % 80;
        g_Wev[i] = wv_w[(size_t)(l * 256 + r) * 336 + 256 + p];
    }
    // biases; bq folds in the constant query time-encoding contribution
    for (int i = idx; i < 2 * 768; i += stride) {
        int l = i / 768; int r = i % 768;
        float v;
        if (r < 256)      v = wk_b[l * 256 + r];
        else if (r < 512) v = wv_b[l * 256 + (r - 256)];
        else {
            int rq = r - 512;
            v = wq_b[l * 256 + rq];
            for (int t = 0; t < 16; t++) {
                float ph = te_phi[l * 16 + t];
                float qt = (t == 0) ? ph : sinf(ph);
                v += wq_w[(size_t)(l * 256 + rq) * 272 + 256 + t] * qt;
            }
        }
        g_b[i] = v;
    }
}

// cbias[l][h*80+p] = sum_c We_k^T[l][p][64h+c] * bq_eff[l][64h+c]
__global__ void pack_cbias_kernel() {
    int idx = blockIdx.x * blockDim.x + threadIdx.x;
    if (idx >= 2 * 320) return;
    int l = idx / 320; int hp = idx % 320;
    int h = hp / 80, p = hp % 80;
    const float* wt = g_WeTk + (size_t)(l * 80 + p) * 256 + 64 * h;
    const float* bq = g_b + l * 768 + 512 + 64 * h;
    float s = 0.f;
    for (int c = 0; c < 64; c++) s += wt[c] * bq[c];
    g_cb[idx] = s;
}

// build [edge_feat | tenc_l] per edge
__global__ void build_msge_kernel(const float* __restrict__ ef, const float* __restrict__ et,
                                  const float* __restrict__ te_w, const float* __restrict__ te_phi, int l) {
    int idx = blockIdx.x * blockDim.x + threadIdx.x;
    int stride = gridDim.x * blockDim.x;
    for (int i = idx; i < E_ * 80; i += stride) {
        int e = i / 80, j = i % 80;
        float v;
        if (j < 64) {
            v = ef[(size_t)e * 64 + j];
        } else {
            int t = j - 64;
            float wt = (-et[e]) * te_w[l * 16 + t] + te_phi[l * 16 + t];
            v = (t == 0) ? wt : sinf(wt);
        }
        g_msge[i] = v;
    }
}

__global__ void zero_agg_kernel() {
    int idx = blockIdx.x * blockDim.x + threadIdx.x;
    if (idx < N_ * 64) reinterpret_cast<float4*>(g_agg)[idx] = make_float4(0.f, 0.f, 0.f, 0.f);
    if (idx < N_ * 20) reinterpret_cast<float4*>(g_aggm)[idx] = make_float4(0.f, 0.f, 0.f, 0.f);
    if (idx < N_) g_nrm[idx] = 0.f;
}

// ---------------- fp32x2 tiled GEMM: C = A(MxK) @ W(NoutxK)^T (+bias) (+gelu) ----------------
// 128x128 tile, 256 threads, thread tile 8(i,pair-packed) x 8(j).
template <bool GELU>
__global__ __launch_bounds__(256)
void gemm2_kernel(const float* __restrict__ A, int lda,
                  const float* __restrict__ W, int ldw,
                  const float* __restrict__ bias,
                  float* __restrict__ C, int ldc,
                  int M, int Nout, int K) {
    __shared__ __align__(16) float As[16][130];
    __shared__ __align__(16) float Bs[16][130];
    int t  = threadIdx.x;
    int bm = blockIdx.x * 128, bn = blockIdx.y * 128;
    int tx = t & 15, ty = t >> 4;
    int lr = t >> 2, lc4 = (t & 3) * 4;
    unsigned long long acc[4][8] = {};
    for (int k0 = 0; k0 < K; k0 += 16) {
#pragma unroll
        for (int half = 0; half < 2; half++) {
            int r = lr + half * 64;
            int ar = bm + r;
            float4 av = make_float4(0.f, 0.f, 0.f, 0.f);
            if (ar < M) av = *reinterpret_cast<const float4*>(A + (size_t)ar * lda + k0 + lc4);
            As[lc4 + 0][r] = av.x; As[lc4 + 1][r] = av.y;
            As[lc4 + 2][r] = av.z; As[lc4 + 3][r] = av.w;
            int wr = bn + r;
            float4 wv = make_float4(0.f, 0.f, 0.f, 0.f);
            if (wr < Nout) wv = *reinterpret_cast<const float4*>(W + (size_t)wr * ldw + k0 + lc4);
            Bs[lc4 + 0][r] = wv.x; Bs[lc4 + 1][r] = wv.y;
            Bs[lc4 + 2][r] = wv.z; Bs[lc4 + 3][r] = wv.w;
        }
        __syncthreads();
#pragma unroll
        for (int kk = 0; kk < 16; kk++) {
            unsigned long long ap[4];
#pragma unroll
            for (int ip = 0; ip < 4; ip++)
                ap[ip] = *reinterpret_cast<const unsigned long long*>(&As[kk][ty * 8 + ip * 2]);
#pragma unroll
            for (int j = 0; j < 8; j++) {
                unsigned long long bb = pk2(Bs[kk][tx + 16 * j]);
#pragma unroll
                for (int ip = 0; ip < 4; ip++)
                    acc[ip][j] = ffma2(ap[ip], bb, acc[ip][j]);
            }
        }
        __syncthreads();
    }
#pragma unroll
    for (int j = 0; j < 8; j++) {
        int col = bn + tx + 16 * j;
        if (col >= Nout) continue;
        float bz = bias ? bias[col] : 0.f;
#pragma unroll
        for (int ip = 0; ip < 4; ip++) {
            float2 v = up2(acc[ip][j]);
            float o0 = v.x + bz, o1 = v.y + bz;
            if (GELU) {
                o0 = 0.5f * o0 * (1.0f + erff(o0 * 0.70710678118654752f));
                o1 = 0.5f * o1 * (1.0f + erff(o1 * 0.70710678118654752f));
            }
            int r0 = bm + ty * 8 + ip * 2;
            if (r0 < M)     C[(size_t)r0 * ldc + col] = o0;
            if (r0 + 1 < M) C[(size_t)(r0 + 1) * ldc + col] = o1;
        }
    }
}

// ---------------- per-edge attention + scatter (fused) ----------------
__device__ __forceinline__ void red_add4(float* p, float a, float b, float c, float d) {
    asm volatile("red.global.add.v4.f32 [%0], {%1, %2, %3, %4};"
                 :: "l"(p), "f"(a), "f"(b), "f"(c), "f"(d) : "memory");
}

__global__ __launch_bounds__(256)
void edge_attn_kernel(const int* __restrict__ src, const int* __restrict__ dst, int l) {
    int e = (blockIdx.x * blockDim.x + threadIdx.x) >> 5;
    int lane = threadIdx.x & 31;
    if (e >= E_) return;
    int s = src[e], d = dst[e];
    int jn = dst[d];                       // faithful h_dst[dst] quirk
    const float* bb = g_b + l * 768;
    size_t sb = (size_t)s  * 768;
    size_t jb = (size_t)jn * 768;
    int o = lane * 8;
    int head = lane >> 3, hl = lane & 7;

    // node QK part: (HQ[jn]+bq) . (HK[s]+bk) over this lane's 8 dims
    float acc = 0.f;
#pragma unroll
    for (int i = 0; i < 8; i += 4) {
        float4 hk = *reinterpret_cast<const float4*>(g_hkvq + sb + o + i);
        float4 bk = *reinterpret_cast<const float4*>(bb + o + i);
        float4 hq = *reinterpret_cast<const float4*>(g_hkvq + jb + 512 + o + i);
        float4 bq = *reinterpret_cast<const float4*>(bb + 512 + o + i);
        acc += (hk.x + bk.x) * (hq.x + bq.x) + (hk.y + bk.y) * (hq.y + bq.y)
             + (hk.z + bk.z) * (hq.z + bq.z) + (hk.w + bk.w) * (hq.w + bq.w);
    }
    // edge-K part: P[jn,head,:] . msg  (P already includes bq contribution)
    {
        const float* Pr = g_P + (size_t)jn * 320 + head * 80 + hl;
        const float* mg = g_msge + (size_t)e * 80 + hl;
#pragma unroll
        for (int tt = 0; tt < 10; tt++) acc += Pr[8 * tt] * mg[8 * tt];
    }
    // reduce within head (8 lanes)
    acc += __shfl_xor_sync(0xffffffffu, acc, 1);
    acc += __shfl_xor_sync(0xffffffffu, acc, 2);
    acc += __shfl_xor_sync(0xffffffffu, acc, 4);
    float sc = fminf(5.0f, fmaxf(-5.0f, acc * 0.125f));
    float a = __expf(sc);
    float sm = a;
    sm += __shfl_xor_sync(0xffffffffu, sm, 8);
    sm += __shfl_xor_sync(0xffffffffu, sm, 16);
    float af = sm * 0.25f;

    // scatter: aggv += af*(HV[s]+bv)
    float v[8];
#pragma unroll
    for (int i = 0; i < 8; i += 4) {
        float4 hv = *reinterpret_cast<const float4*>(g_hkvq + sb + 256 + o + i);
        float4 bv = *reinterpret_cast<const float4*>(bb + 256 + o + i);
        v[i + 0] = (hv.x + bv.x) * af;
        v[i + 1] = (hv.y + bv.y) * af;
        v[i + 2] = (hv.z + bv.z) * af;
        v[i + 3] = (hv.w + bv.w) * af;
    }
    float* ag = g_agg + (size_t)d * 256 + o;
    red_add4(ag,     v[0], v[1], v[2], v[3]);
    red_add4(ag + 4, v[4], v[5], v[6], v[7]);
    // scatter: aggm += af*msg (80 floats by lanes 0..19)
    if (lane < 20) {
        float4 m4 = *reinterpret_cast<const float4*>(g_msge + (size_t)e * 80 + lane * 4);
        red_add4(g_aggm + (size_t)d * 80 + lane * 4, m4.x * af, m4.y * af, m4.z * af, m4.w * af);
    }
    if (lane == 0) atomicAdd(g_nrm + d, af);
}

// ---------------- node update: h = LN(h + LN((agg+agg2)/(nrm+1e-8))) ----------------
__global__ __launch_bounds__(256)
void node_update_kernel(const float* __restrict__ aw, const float* __restrict__ ab,
                        const float* __restrict__ lw, const float* __restrict__ lb) {
    int n = (blockIdx.x * blockDim.x + threadIdx.x) >> 5;
    int lane = threadIdx.x & 31;
    if (n >= N_) return;
    size_t base = (size_t)n * 256;
    int o = lane * 8;
    float inv = 1.0f / (g_nrm[n] + 1e-8f);
    float x[8];
    {
        float4 a0 = *reinterpret_cast<const float4*>(g_agg  + base + o);
        float4 a1 = *reinterpret_cast<const float4*>(g_agg  + base + o + 4);
        float4 b0 = *reinterpret_cast<const float4*>(g_agg2 + base + o);
        float4 b1 = *reinterpret_cast<const float4*>(g_agg2 + base + o + 4);
        x[0] = (a0.x + b0.x) * inv; x[1] = (a0.y + b0.y) * inv;
        x[2] = (a0.z + b0.z) * inv; x[3] = (a0.w + b0.w) * inv;
        x[4] = (a1.x + b1.x) * inv; x[5] = (a1.y + b1.y) * inv;
        x[6] = (a1.z + b1.z) * inv; x[7] = (a1.w + b1.w) * inv;
    }
    float s = 0.f;
#pragma unroll
    for (int i = 0; i < 8; i++) s += x[i];
#pragma unroll
    for (int m = 16; m >= 1; m >>= 1) s += __shfl_xor_sync(0xffffffffu, s, m);
    float mean = s * (1.0f / 256.0f);
    float vv = 0.f;
#pragma unroll
    for (int i = 0; i < 8; i++) { float dx = x[i] - mean; vv += dx * dx; }
#pragma unroll
    for (int m = 16; m >= 1; m >>= 1) vv += __shfl_xor_sync(0xffffffffu, vv, m);
    float is = rsqrtf(vv * (1.0f / 256.0f) + 1e-5f);
    float r[8];
#pragma unroll
    for (int i = 0; i < 8; i++) {
        float hn = (x[i] - mean) * is * aw[o + i] + ab[o + i];
        r[i] = g_h[base + o + i] + hn;
    }
    float s2 = 0.f;
#pragma unroll
    for (int i = 0; i < 8; i++) s2 += r[i];
#pragma unroll
    for (int m = 16; m >= 1; m >>= 1) s2 += __shfl_xor_sync(0xffffffffu, s2, m);
    float mean2 = s2 * (1.0f / 256.0f);
    float v2 = 0.f;
#pragma unroll
    for (int i = 0; i < 8; i++) { float dx = r[i] - mean2; v2 += dx * dx; }
#pragma unroll
    for (int m = 16; m >= 1; m >>= 1) v2 += __shfl_xor_sync(0xffffffffu, v2, m);
    float is2 = rsqrtf(v2 * (1.0f / 256.0f) + 1e-5f);
#pragma unroll
    for (int i = 0; i < 8; i++)
        g_h[base + o + i] = (r[i] - mean2) * is2 * lw[o + i] + lb[o + i];
}

// ---------------- launch ----------------
extern "C" void kernel_launch(void* const* d_in, const int* in_sizes, int n_in,
                              void* d_out, int out_size) {
    const float* node_feat  = (const float*)d_in[0];
    const float* memory     = (const float*)d_in[1];
    const int*   eidx       = (const int*)  d_in[2];
    const float* edge_feat  = (const float*)d_in[3];
    const float* edge_times = (const float*)d_in[4];
    const float* in_w       = (const float*)d_in[5];
    const float* in_b       = (const float*)d_in[6];
    const float* te_w       = (const float*)d_in[7];
    const float* te_phi     = (const float*)d_in[8];
    const float* wq_w       = (const float*)d_in[9];
    const float* wq_b       = (const float*)d_in[10];
    const float* wk_w       = (const float*)d_in[11];
    const float* wk_b       = (const float*)d_in[12];
    const float* wv_w       = (const float*)d_in[13];
    const float* wv_b       = (const float*)d_in[14];
    const float* attn_ln_w  = (const float*)d_in[15];
    const float* attn_ln_b  = (const float*)d_in[16];
    const float* ln_w       = (const float*)d_in[17];
    const float* ln_b       = (const float*)d_in[18];
    const float* out_w      = (const float*)d_in[19];
    const float* out_b      = (const float*)d_in[20];
    const int* src = eidx;
    const int* dst = eidx + E_;
    float* out = (float*)d_out;

    float *pX, *ph, *phkvq, *pmsge, *pP, *pAggm, *pAgg2, *pWh, *pWeTk, *pWev, *pCb;
    cudaGetSymbolAddress((void**)&pX,    g_X);
    cudaGetSymbolAddress((void**)&ph,    g_h);
    cudaGetSymbolAddress((void**)&phkvq, g_hkvq);
    cudaGetSymbolAddress((void**)&pmsge, g_msge);
    cudaGetSymbolAddress((void**)&pP,    g_P);
    cudaGetSymbolAddress((void**)&pAggm, g_aggm);
    cudaGetSymbolAddress((void**)&pAgg2, g_agg2);
    cudaGetSymbolAddress((void**)&pWh,   g_Wh);
    cudaGetSymbolAddress((void**)&pWeTk, g_WeTk);
    cudaGetSymbolAddress((void**)&pWev,  g_Wev);
    cudaGetSymbolAddress((void**)&pCb,   g_cb);

    const int GX = (N_ + 127) / 128;   // 391

    pack_x_kernel<<<4096, 256>>>(node_feat, memory);
    pack_weights_kernel<<<1024, 256>>>(wk_w, wk_b, wv_w, wv_b, wq_w, wq_b, te_phi);
    pack_cbias_kernel<<<3, 256>>>();

    // h = [node_feat|memory] @ in_w^T + in_b
    gemm2_kernel<false><<<dim3(GX, 2), 256>>>(pX, 256, in_w, 256, in_b, ph, 256,
                                              N_, 256, 256);

    for (int l = 0; l < 2; l++) {
        build_msge_kernel<<<16384, 256>>>(edge_feat, edge_times, te_w, te_phi, l);
        // HKVQ = h @ Wh^T  (N x 768, K=256)
        gemm2_kernel<false><<<dim3(GX, 6), 256>>>(ph, 256, pWh + (size_t)l * 768 * 256, 256,
                                                  nullptr, phkvq, 768, N_, 768, 256);
        // P[:, h] = HQ_h @ We_k_h + cbias   (per head: N x 80, K=64)
        for (int hd = 0; hd < 4; hd++) {
            gemm2_kernel<false><<<dim3(GX, 1), 256>>>(
                phkvq + 512 + 64 * hd, 768,
                pWeTk + (size_t)l * 80 * 256 + 64 * hd, 256,
                pCb + l * 320 + 80 * hd,
                pP + 80 * hd, 320,
                N_, 80, 64);
        }
        zero_agg_kernel<<<12500, 256>>>();
        edge_attn_kernel<<<25000, 256>>>(src, dst, l);
        // agg2 = aggm @ We_v^T  (N x 256, K=80)
        gemm2_kernel<false><<<dim3(GX, 2), 256>>>(pAggm, 80, pWev + (size_t)l * 256 * 80, 80,
                                                  nullptr, pAgg2, 256, N_, 256, 80);
        node_update_kernel<<<6250, 256>>>(attn_ln_w + l * 256, attn_ln_b + l * 256,
                                          ln_w + l * 256, ln_b + l * 256);
    }

    // out = gelu(h @ out_w^T + out_b)
    gemm2_kernel<true><<<dim3(GX, 1), 256>>>(ph, 256, out_w, 256, out_b, out, 64,
                                             N_, 64, 256);
}

// round 4
// speedup vs baseline: 1.5571x; 1.1027x over previous
#include <cuda_runtime.h>
#include <cuda_bf16.h>
#include <math.h>
#include <stdint.h>

static constexpr int N_ = 50000;
static constexpr int E_ = 200000;

// ---------------- scratch ----------------
__device__ __nv_bfloat16 g_X3   [(size_t)N_ * 768];   // split [hi|lo|hi] of [nf|mem]
__device__ float         g_h    [(size_t)N_ * 256];
__device__ __nv_bfloat16 g_h3   [(size_t)N_ * 768];   // split of h
__device__ float         g_hkvqp[(size_t)N_ * 1152];  // [HK|HV|HQ|P(320)|pad]
__device__ float         g_msge [(size_t)E_ * 80];
__device__ float         g_agg  [(size_t)N_ * 256];
__device__ float         g_agg2 [(size_t)N_ * 256];
__device__ float         g_aggm [(size_t)N_ * 80];
__device__ __nv_bfloat16 g_aggm3[(size_t)N_ * 256];   // split of aggm (K0=80, pad 256)
__device__ float         g_nrm  [N_];
__device__ float         g_Wall [2 * 1152 * 256];     // fp32 [Wk;Wv;Wq;Wfused;0]
__device__ __nv_bfloat16 g_Wall3[2 * 1152 * 768];
__device__ float         g_bias1152[2 * 1152];        // cb at rows 768..1087
__device__ __nv_bfloat16 g_Win3 [256 * 768];
__device__ float         g_Wev  [2 * 256 * 80];
__device__ __nv_bfloat16 g_Wev3 [2 * 256 * 256];
__device__ __nv_bfloat16 g_Wout3[64 * 768];
__device__ float         g_b    [2 * 768];            // [bk|bv|bq_eff]

// ---------------- ptx helpers (family-safe: all sm_80 baseline) ----------------
__device__ __forceinline__ uint32_t smem_u32(const void* p) {
    uint32_t a;
    asm("{ .reg .u64 t; cvta.to.shared.u64 t, %1; cvt.u32.u64 %0, t; }" : "=r"(a) : "l"(p));
    return a;
}
__device__ __forceinline__ void cp16(uint32_t dst, const void* src, int pred) {
    asm volatile(
        "{\n\t.reg .pred p;\n\t"
        "setp.ne.u32 p, %2, 0;\n\t"
        "@p cp.async.ca.shared.global [%0], [%1], 16;\n\t"
        "@!p cp.async.ca.shared.global [%0], [%1], 16, 0;\n\t}"
        :: "r"(dst), "l"(src), "r"(pred) : "memory");
}
__device__ __forceinline__ void cp_commit() {
    asm volatile("cp.async.commit_group;" ::: "memory");
}
__device__ __forceinline__ void ldm4(uint32_t* r, uint32_t addr) {
    asm volatile("ldmatrix.sync.aligned.m8n8.x4.shared.b16 {%0,%1,%2,%3}, [%4];"
                 : "=r"(r[0]), "=r"(r[1]), "=r"(r[2]), "=r"(r[3]) : "r"(addr));
}
__device__ __forceinline__ void ldm2(uint32_t* r, uint32_t addr) {
    asm volatile("ldmatrix.sync.aligned.m8n8.x2.shared.b16 {%0,%1}, [%2];"
                 : "=r"(r[0]), "=r"(r[1]) : "r"(addr));
}
__device__ __forceinline__ void mma16816(float* c, const uint32_t* a, const uint32_t* b) {
    asm volatile(
        "mma.sync.aligned.m16n8k16.row.col.f32.bf16.bf16.f32 "
        "{%0,%1,%2,%3},{%4,%5,%6,%7},{%8,%9},{%0,%1,%2,%3};"
        : "+f"(c[0]), "+f"(c[1]), "+f"(c[2]), "+f"(c[3])
        : "r"(a[0]), "r"(a[1]), "r"(a[2]), "r"(a[3]), "r"(b[0]), "r"(b[1]));
}

// ---------------- mma.sync GEMM: C(M x noutC) = A3(M x ka) @ W3(noutW x ka)^T ----------------
// 128x128 CTA tile, 8 warps (2M x 4N), K chunks of 32, cp.async double-buffered.
template <bool GELU, bool SPLIT>
__global__ __launch_bounds__(256)
void mma_gemm(const __nv_bfloat16* __restrict__ A3, int ka,
              const __nv_bfloat16* __restrict__ W3, int noutW,
              const float* __restrict__ bias,
              float* __restrict__ C, int ldc, int M, int noutC,
              __nv_bfloat16* __restrict__ S3) {
    constexpr int SAS = 40;                      // padded smem stride (elems)
    constexpr int BUF = 128 * SAS;               // elems per buffer
    __shared__ __align__(16) __nv_bfloat16 sA[2][BUF];
    __shared__ __align__(16) __nv_bfloat16 sB[2][BUF];

    int tid = threadIdx.x, lane = tid & 31, wid = tid >> 5;
    int wm = wid & 1, wn = wid >> 1;
    int bm = blockIdx.x * 128, bn = blockIdx.y * 128;
    int NC = ka >> 5;
    uint32_t sAu = smem_u32(sA), sBu = smem_u32(sB);

    // ldmatrix per-lane offsets
    int arow = (lane & 7) + ((lane >> 3) & 1) * 8;
    int acol = ((lane >> 4) & 1) * 8;
    int brow = lane & 7;
    int bk   = ((lane >> 3) & 1) * 8;

    float acc[4][4][4] = {};

    // loader: thread covers ids {tid, tid+256}; id -> row = id>>2, colgroup = id&3
    int lrow0 = tid >> 2, lcg0 = (tid & 3) * 8;
    int lrow1 = (tid + 256) >> 2, lcg1 = ((tid + 256) & 3) * 8;

#define LOADC(c, buf)                                                                  \
    {                                                                                  \
        int _c32 = (c) * 32;                                                           \
        uint32_t _ab = sAu + (buf) * (BUF * 2);                                        \
        uint32_t _bb = sBu + (buf) * (BUF * 2);                                        \
        int gr0 = bm + lrow0; int pa0 = gr0 < M; int ga0 = pa0 ? gr0 : 0;              \
        cp16(_ab + (lrow0 * SAS + lcg0) * 2, A3 + (size_t)ga0 * ka + _c32 + lcg0, pa0);\
        int wr0 = bn + lrow0; int pb0 = wr0 < noutW; int wa0 = pb0 ? wr0 : 0;          \
        cp16(_bb + (lrow0 * SAS + lcg0) * 2, W3 + (size_t)wa0 * ka + _c32 + lcg0, pb0);\
        int gr1 = bm + lrow1; int pa1 = gr1 < M; int ga1 = pa1 ? gr1 : 0;              \
        cp16(_ab + (lrow1 * SAS + lcg1) * 2, A3 + (size_t)ga1 * ka + _c32 + lcg1, pa1);\
        int wr1 = bn + lrow1; int pb1 = wr1 < noutW; int wa1 = pb1 ? wr1 : 0;          \
        cp16(_bb + (lrow1 * SAS + lcg1) * 2, W3 + (size_t)wa1 * ka + _c32 + lcg1, pb1);\
        cp_commit();                                                                   \
    }

    LOADC(0, 0);
    for (int c = 0; c < NC; c++) {
        if (c + 1 < NC) {
            LOADC(c + 1, (c + 1) & 1);
            asm volatile("cp.async.wait_group 1;" ::: "memory");
        } else {
            asm volatile("cp.async.wait_group 0;" ::: "memory");
        }
        __syncthreads();
        uint32_t sAb = sAu + (c & 1) * (BUF * 2);
        uint32_t sBb = sBu + (c & 1) * (BUF * 2);
#pragma unroll
        for (int ks = 0; ks < 2; ks++) {
            uint32_t af[4][4];
#pragma unroll
            for (int mf = 0; mf < 4; mf++)
                ldm4(af[mf], sAb + ((wm * 64 + mf * 16 + arow) * SAS + ks * 16 + acol) * 2);
            uint32_t bf[4][2];
#pragma unroll
            for (int nf = 0; nf < 4; nf++)
                ldm2(bf[nf], sBb + ((wn * 32 + nf * 8 + brow) * SAS + ks * 16 + bk) * 2);
#pragma unroll
            for (int mf = 0; mf < 4; mf++)
#pragma unroll
                for (int nf = 0; nf < 4; nf++)
                    mma16816(acc[mf][nf], af[mf], bf[nf]);
        }
        __syncthreads();
    }

    // epilogue
    int cr = lane >> 2, cc = (lane & 3) * 2;
#pragma unroll
    for (int mf = 0; mf < 4; mf++) {
#pragma unroll
        for (int nf = 0; nf < 4; nf++) {
            int col = bn + wn * 32 + nf * 8 + cc;
            if (col >= noutC) continue;
            float bz0 = bias ? bias[col] : 0.f;
            float bz1 = bias ? bias[col + 1] : 0.f;
#pragma unroll
            for (int hh = 0; hh < 2; hh++) {
                int row = bm + wm * 64 + mf * 16 + cr + hh * 8;
                if (row >= M) continue;
                float v0 = acc[mf][nf][hh * 2 + 0] + bz0;
                float v1 = acc[mf][nf][hh * 2 + 1] + bz1;
                if (GELU) {
                    v0 = 0.5f * v0 * (1.0f + erff(v0 * 0.70710678118654752f));
                    v1 = 0.5f * v1 * (1.0f + erff(v1 * 0.70710678118654752f));
                }
                *reinterpret_cast<float2*>(C + (size_t)row * ldc + col) = make_float2(v0, v1);
                if (SPLIT) {
                    size_t b3 = (size_t)row * 3 * noutC;
                    __nv_bfloat16 h0 = __float2bfloat16(v0);
                    __nv_bfloat16 l0 = __float2bfloat16(v0 - __bfloat162float(h0));
                    __nv_bfloat16 h1 = __float2bfloat16(v1);
                    __nv_bfloat16 l1 = __float2bfloat16(v1 - __bfloat162float(h1));
                    S3[b3 + col] = h0; S3[b3 + col + 1] = h1;
                    S3[b3 + noutC + col] = l0; S3[b3 + noutC + col + 1] = l1;
                    S3[b3 + 2 * noutC + col] = h0; S3[b3 + 2 * noutC + col + 1] = h1;
                }
            }
        }
    }
#undef LOADC
}

// ---------------- pack / conversion ----------------
__global__ void pack_x3_kernel(const float* __restrict__ nf, const float* __restrict__ mem) {
    int idx = blockIdx.x * blockDim.x + threadIdx.x;
    int stride = gridDim.x * blockDim.x;
    for (int i = idx; i < N_ * 256; i += stride) {
        int n = i >> 8, j = i & 255;
        float v = (j < 128) ? nf[n * 128 + j] : mem[n * 128 + (j - 128)];
        __nv_bfloat16 hi = __float2bfloat16(v);
        __nv_bfloat16 lo = __float2bfloat16(v - __bfloat162float(hi));
        size_t b = (size_t)n * 768;
        g_X3[b + j] = hi; g_X3[b + 256 + j] = lo; g_X3[b + 512 + j] = hi;
    }
}

__global__ void pack_b_kernel(const float* __restrict__ wk_b, const float* __restrict__ wv_b,
                              const float* __restrict__ wq_b, const float* __restrict__ wq_w,
                              const float* __restrict__ te_phi) {
    int idx = blockIdx.x * blockDim.x + threadIdx.x;
    if (idx >= 2 * 768) return;
    int l = idx / 768, r = idx % 768;
    float v;
    if (r < 256)      v = wk_b[l * 256 + r];
    else if (r < 512) v = wv_b[l * 256 + (r - 256)];
    else {
        int rq = r - 512;
        v = wq_b[l * 256 + rq];
        for (int t = 0; t < 16; t++) {
            float ph = te_phi[l * 16 + t];
            float qt = (t == 0) ? ph : sinf(ph);
            v += wq_w[(size_t)(l * 256 + rq) * 272 + 256 + t] * qt;
        }
    }
    g_b[idx] = v;
}

__global__ void pack_wall_base_kernel(const float* __restrict__ wk_w, const float* __restrict__ wv_w,
                                      const float* __restrict__ wq_w) {
    int idx = blockIdx.x * blockDim.x + threadIdx.x;
    int stride = gridDim.x * blockDim.x;
    for (int i = idx; i < 2 * 1152 * 256; i += stride) {
        int l = i / (1152 * 256); int r = (i / 256) % 1152; int k = i & 255;
        if (r < 256)      g_Wall[i] = wk_w[(size_t)(l * 256 + r)       * 336 + k];
        else if (r < 512) g_Wall[i] = wv_w[(size_t)(l * 256 + (r-256)) * 336 + k];
        else if (r < 768) g_Wall[i] = wq_w[(size_t)(l * 256 + (r-512)) * 272 + k];
        else if (r >= 1088) g_Wall[i] = 0.f;
    }
    for (int i = idx; i < 2 * 1152; i += stride) {
        int r = i % 1152;
        if (r < 768 || r >= 1088) g_bias1152[i] = 0.f;
    }
    for (int i = idx; i < 2 * 256 * 80; i += stride) {
        int l = i / (256 * 80); int r = (i / 80) % 256; int p = i % 80;
        g_Wev[i] = wv_w[(size_t)(l * 256 + r) * 336 + 256 + p];
    }
}

// rows 768..1087 of W_all: (WeTk blockdiag) @ Wq_h, plus cb bias
__global__ __launch_bounds__(256)
void pack_wall_fused_kernel(const float* __restrict__ wk_w, const float* __restrict__ wq_w) {
    __shared__ float wk_s[64];
    int b = blockIdx.x;               // 0..639
    int l = b / 320, q = b % 320;
    int hd = q / 80, p = q % 80;
    int t = threadIdx.x;
    if (t < 64) wk_s[t] = wk_w[(size_t)(l * 256 + 64 * hd + t) * 336 + 256 + p];
    __syncthreads();
    float acc = 0.f;
    for (int c = 0; c < 64; c++)
        acc += wk_s[c] * wq_w[(size_t)(l * 256 + 64 * hd + c) * 272 + t];
    g_Wall[(size_t)l * 1152 * 256 + (size_t)(768 + q) * 256 + t] = acc;
    if (t == 0) {
        float cb = 0.f;
        for (int c = 0; c < 64; c++) cb += wk_s[c] * g_b[l * 768 + 512 + 64 * hd + c];
        g_bias1152[l * 1152 + 768 + q] = cb;
    }
}

// split fp32 (rows x K0) -> bf16 (rows x KA); weight pattern [hi|hi|lo], act pattern [hi|lo|hi]
__global__ void conv_split_kernel(const float* __restrict__ src, int rows, int K0,
                                  __nv_bfloat16* __restrict__ dst, int KA, int actPat) {
    int idx = blockIdx.x * blockDim.x + threadIdx.x;
    int stride = gridDim.x * blockDim.x;
    long total = (long)rows * KA;
    for (long i = idx; i < total; i += stride) {
        int r = (int)(i / KA); int j = (int)(i % KA);
        __nv_bfloat16 o = __float2bfloat16(0.f);
        int blk = j / K0, jj = j % K0;
        if (blk < 3) {
            float v = src[(size_t)r * K0 + jj];
            __nv_bfloat16 hi = __float2bfloat16(v);
            if (blk == 0) o = hi;
            else {
                __nv_bfloat16 lo = __float2bfloat16(v - __bfloat162float(hi));
                if (actPat) o = (blk == 1) ? lo : hi;
                else        o = (blk == 1) ? hi : lo;
            }
        }
        dst[i] = o;
    }
}

__global__ void build_msge_kernel(const float* __restrict__ ef, const float* __restrict__ et,
                                  const float* __restrict__ te_w, const float* __restrict__ te_phi, int l) {
    int idx = blockIdx.x * blockDim.x + threadIdx.x;
    int stride = gridDim.x * blockDim.x;
    for (int i = idx; i < E_ * 80; i += stride) {
        int e = i / 80, j = i % 80;
        float v;
        if (j < 64) v = ef[(size_t)e * 64 + j];
        else {
            int t = j - 64;
            float wt = (-et[e]) * te_w[l * 16 + t] + te_phi[l * 16 + t];
            v = (t == 0) ? wt : sinf(wt);
        }
        g_msge[i] = v;
    }
}

__global__ void zero_agg_kernel() {
    int idx = blockIdx.x * blockDim.x + threadIdx.x;
    if (idx < N_ * 64) reinterpret_cast<float4*>(g_agg)[idx] = make_float4(0.f, 0.f, 0.f, 0.f);
    if (idx < N_ * 20) reinterpret_cast<float4*>(g_aggm)[idx] = make_float4(0.f, 0.f, 0.f, 0.f);
    if (idx < N_) g_nrm[idx] = 0.f;
}

// ---------------- edge attention + scatter ----------------
__device__ __forceinline__ void red_add4(float* p, float a, float b, float c, float d) {
    asm volatile("red.global.add.v4.f32 [%0], {%1, %2, %3, %4};"
                 :: "l"(p), "f"(a), "f"(b), "f"(c), "f"(d) : "memory");
}

__global__ __launch_bounds__(256)
void edge_attn_kernel(const int* __restrict__ src, const int* __restrict__ dst, int l) {
    int e = (blockIdx.x * blockDim.x + threadIdx.x) >> 5;
    int lane = threadIdx.x & 31;
    if (e >= E_) return;
    int s = src[e], d = dst[e];
    int jn = dst[d];
    const float* bb = g_b + l * 768;
    size_t sb = (size_t)s  * 1152;
    size_t jb = (size_t)jn * 1152;
    int o = lane * 8;
    int head = lane >> 3, hl = lane & 7;

    float acc = 0.f;
#pragma unroll
    for (int i = 0; i < 8; i += 4) {
        float4 hk = *reinterpret_cast<const float4*>(g_hkvqp + sb + o + i);
        float4 bk = *reinterpret_cast<const float4*>(bb + o + i);
        float4 hq = *reinterpret_cast<const float4*>(g_hkvqp + jb + 512 + o + i);
        float4 bq = *reinterpret_cast<const float4*>(bb + 512 + o + i);
        acc += (hk.x + bk.x) * (hq.x + bq.x) + (hk.y + bk.y) * (hq.y + bq.y)
             + (hk.z + bk.z) * (hq.z + bq.z) + (hk.w + bk.w) * (hq.w + bq.w);
    }
    {
        const float* Pr = g_hkvqp + jb + 768 + head * 80 + hl;
        const float* mg = g_msge + (size_t)e * 80 + hl;
#pragma unroll
        for (int tt = 0; tt < 10; tt++) acc += Pr[8 * tt] * mg[8 * tt];
    }
    acc += __shfl_xor_sync(0xffffffffu, acc, 1);
    acc += __shfl_xor_sync(0xffffffffu, acc, 2);
    acc += __shfl_xor_sync(0xffffffffu, acc, 4);
    float sc = fminf(5.0f, fmaxf(-5.0f, acc * 0.125f));
    float a = __expf(sc);
    float sm = a;
    sm += __shfl_xor_sync(0xffffffffu, sm, 8);
    sm += __shfl_xor_sync(0xffffffffu, sm, 16);
    float af = sm * 0.25f;

    float v[8];
#pragma unroll
    for (int i = 0; i < 8; i += 4) {
        float4 hv = *reinterpret_cast<const float4*>(g_hkvqp + sb + 256 + o + i);
        float4 bv = *reinterpret_cast<const float4*>(bb + 256 + o + i);
        v[i + 0] = (hv.x + bv.x) * af;
        v[i + 1] = (hv.y + bv.y) * af;
        v[i + 2] = (hv.z + bv.z) * af;
        v[i + 3] = (hv.w + bv.w) * af;
    }
    float* ag = g_agg + (size_t)d * 256 + o;
    red_add4(ag,     v[0], v[1], v[2], v[3]);
    red_add4(ag + 4, v[4], v[5], v[6], v[7]);
    if (lane < 20) {
        float4 m4 = *reinterpret_cast<const float4*>(g_msge + (size_t)e * 80 + lane * 4);
        red_add4(g_aggm + (size_t)d * 80 + lane * 4, m4.x * af, m4.y * af, m4.z * af, m4.w * af);
    }
    if (lane == 0) atomicAdd(g_nrm + d, af);
}

// ---------------- node update: h = LN(h + LN((agg+agg2)/(nrm+eps))); writes h and h3 ----------------
__global__ __launch_bounds__(256)
void node_update_kernel(const float* __restrict__ aw, const float* __restrict__ ab,
                        const float* __restrict__ lw, const float* __restrict__ lb) {
    int n = (blockIdx.x * blockDim.x + threadIdx.x) >> 5;
    int lane = threadIdx.x & 31;
    if (n >= N_) return;
    size_t base = (size_t)n * 256;
    int o = lane * 8;
    float inv = 1.0f / (g_nrm[n] + 1e-8f);
    float x[8];
    {
        float4 a0 = *reinterpret_cast<const float4*>(g_agg  + base + o);
        float4 a1 = *reinterpret_cast<const float4*>(g_agg  + base + o + 4);
        float4 b0 = *reinterpret_cast<const float4*>(g_agg2 + base + o);
        float4 b1 = *reinterpret_cast<const float4*>(g_agg2 + base + o + 4);
        x[0] = (a0.x + b0.x) * inv; x[1] = (a0.y + b0.y) * inv;
        x[2] = (a0.z + b0.z) * inv; x[3] = (a0.w + b0.w) * inv;
        x[4] = (a1.x + b1.x) * inv; x[5] = (a1.y + b1.y) * inv;
        x[6] = (a1.z + b1.z) * inv; x[7] = (a1.w + b1.w) * inv;
    }
    float s = 0.f;
#pragma unroll
    for (int i = 0; i < 8; i++) s += x[i];
#pragma unroll
    for (int m = 16; m >= 1; m >>= 1) s += __shfl_xor_sync(0xffffffffu, s, m);
    float mean = s * (1.0f / 256.0f);
    float vv = 0.f;
#pragma unroll
    for (int i = 0; i < 8; i++) { float dx = x[i] - mean; vv += dx * dx; }
#pragma unroll
    for (int m = 16; m >= 1; m >>= 1) vv += __shfl_xor_sync(0xffffffffu, vv, m);
    float is = rsqrtf(vv * (1.0f / 256.0f) + 1e-5f);
    float r[8];
#pragma unroll
    for (int i = 0; i < 8; i++) {
        float hn = (x[i] - mean) * is * aw[o + i] + ab[o + i];
        r[i] = g_h[base + o + i] + hn;
    }
    float s2 = 0.f;
#pragma unroll
    for (int i = 0; i < 8; i++) s2 += r[i];
#pragma unroll
    for (int m = 16; m >= 1; m >>= 1) s2 += __shfl_xor_sync(0xffffffffu, s2, m);
    float mean2 = s2 * (1.0f / 256.0f);
    float v2 = 0.f;
#pragma unroll
    for (int i = 0; i < 8; i++) { float dx = r[i] - mean2; v2 += dx * dx; }
#pragma unroll
    for (int m = 16; m >= 1; m >>= 1) v2 += __shfl_xor_sync(0xffffffffu, v2, m);
    float is2 = rsqrtf(v2 * (1.0f / 256.0f) + 1e-5f);
    size_t b3 = (size_t)n * 768;
#pragma unroll
    for (int i = 0; i < 8; i++) {
        float hv = (r[i] - mean2) * is2 * lw[o + i] + lb[o + i];
        g_h[base + o + i] = hv;
        __nv_bfloat16 hi = __float2bfloat16(hv);
        __nv_bfloat16 lo = __float2bfloat16(hv - __bfloat162float(hi));
        g_h3[b3 + o + i] = hi;
        g_h3[b3 + 256 + o + i] = lo;
        g_h3[b3 + 512 + o + i] = hi;
    }
}

// ---------------- launch ----------------
extern "C" void kernel_launch(void* const* d_in, const int* in_sizes, int n_in,
                              void* d_out, int out_size) {
    const float* node_feat  = (const float*)d_in[0];
    const float* memory     = (const float*)d_in[1];
    const int*   eidx       = (const int*)  d_in[2];
    const float* edge_feat  = (const float*)d_in[3];
    const float* edge_times = (const float*)d_in[4];
    const float* in_w       = (const float*)d_in[5];
    const float* in_b       = (const float*)d_in[6];
    const float* te_w       = (const float*)d_in[7];
    const float* te_phi     = (const float*)d_in[8];
    const float* wq_w       = (const float*)d_in[9];
    const float* wq_b       = (const float*)d_in[10];
    const float* wk_w       = (const float*)d_in[11];
    const float* wk_b       = (const float*)d_in[12];
    const float* wv_w       = (const float*)d_in[13];
    const float* wv_b       = (const float*)d_in[14];
    const float* attn_ln_w  = (const float*)d_in[15];
    const float* attn_ln_b  = (const float*)d_in[16];
    const float* ln_w       = (const float*)d_in[17];
    const float* ln_b       = (const float*)d_in[18];
    const float* out_w      = (const float*)d_in[19];
    const float* out_b      = (const float*)d_in[20];
    const int* src = eidx;
    const int* dst = eidx + E_;
    float* out = (float*)d_out;

    float *ph, *phkvqp, *pAggm, *pAgg2, *pWall, *pWev, *pBias;
    __nv_bfloat16 *pX3, *ph3, *pAggm3, *pWall3, *pWin3, *pWev3, *pWout3;
    cudaGetSymbolAddress((void**)&ph,     g_h);
    cudaGetSymbolAddress((void**)&phkvqp, g_hkvqp);
    cudaGetSymbolAddress((void**)&pAggm,  g_aggm);
    cudaGetSymbolAddress((void**)&pAgg2,  g_agg2);
    cudaGetSymbolAddress((void**)&pWall,  g_Wall);
    cudaGetSymbolAddress((void**)&pWev,   g_Wev);
    cudaGetSymbolAddress((void**)&pBias,  g_bias1152);
    cudaGetSymbolAddress((void**)&pX3,    g_X3);
    cudaGetSymbolAddress((void**)&ph3,    g_h3);
    cudaGetSymbolAddress((void**)&pAggm3, g_aggm3);
    cudaGetSymbolAddress((void**)&pWall3, g_Wall3);
    cudaGetSymbolAddress((void**)&pWin3,  g_Win3);
    cudaGetSymbolAddress((void**)&pWev3,  g_Wev3);
    cudaGetSymbolAddress((void**)&pWout3, g_Wout3);

    const int GX = (N_ + 127) / 128;  // 391

    pack_x3_kernel<<<4096, 256>>>(node_feat, memory);
    pack_b_kernel<<<6, 256>>>(wk_b, wv_b, wq_b, wq_w, te_phi);
    pack_wall_base_kernel<<<2304, 256>>>(wk_w, wv_w, wq_w);
    pack_wall_fused_kernel<<<640, 256>>>(wk_w, wq_w);
    conv_split_kernel<<<4096, 256>>>(pWall, 2 * 1152, 256, pWall3, 768, 0);
    conv_split_kernel<<<768, 256>>>((const float*)in_w, 256, 256, pWin3, 768, 0);
    conv_split_kernel<<<192, 256>>>((const float*)out_w, 64, 256, pWout3, 768, 0);
    conv_split_kernel<<<512, 256>>>(pWev, 2 * 256, 80, pWev3, 256, 0);

    // h = X @ in_w^T + in_b (also emits h3 split)
    mma_gemm<false, true><<<dim3(GX, 2), 256>>>(pX3, 768, pWin3, 256, in_b,
                                                ph, 256, N_, 256, ph3);

    for (int l = 0; l < 2; l++) {
        build_msge_kernel<<<16384, 256>>>(edge_feat, edge_times, te_w, te_phi, l);
        // [HK|HV|HQ|P] = h @ W_all^T + bias1152
        mma_gemm<false, false><<<dim3(GX, 9), 256>>>(ph3, 768,
                                                     pWall3 + (size_t)l * 1152 * 768, 1152,
                                                     pBias + l * 1152,
                                                     phkvqp, 1152, N_, 1088, nullptr);
        zero_agg_kernel<<<12500, 256>>>();
        edge_attn_kernel<<<25000, 256>>>(src, dst, l);
        conv_split_kernel<<<4096, 256>>>(pAggm, N_, 80, pAggm3, 256, 1);
        // agg2 = aggm @ We_v^T
        mma_gemm<false, false><<<dim3(GX, 2), 256>>>(pAggm3, 256,
                                                     pWev3 + (size_t)l * 256 * 256, 256,
                                                     nullptr, pAgg2, 256, N_, 256, nullptr);
        node_update_kernel<<<6250, 256>>>(attn_ln_w + l * 256, attn_ln_b + l * 256,
                                          ln_w + l * 256, ln_b + l * 256);
    }

    // out = gelu(h @ out_w^T + out_b)
    mma_gemm<true, false><<<dim3(GX, 1), 256>>>(ph3, 768, pWout3, 64, out_b,
                                                out, 64, N_, 64, nullptr);
}

// round 5
// speedup vs baseline: 1.8119x; 1.1637x over previous
#include <cuda_runtime.h>
#include <cuda_bf16.h>
#include <math.h>
#include <stdint.h>

static constexpr int N_ = 50000;
static constexpr int E_ = 200000;

// ---------------- scratch ----------------
__device__ __nv_bfloat16 g_X3   [(size_t)N_ * 768];   // split [hi|lo|hi] of [nf|mem]
__device__ float         g_h    [(size_t)N_ * 256];
__device__ __nv_bfloat16 g_h3   [(size_t)N_ * 768];   // split of h
__device__ float         g_hkvqp[(size_t)N_ * 1152];  // [K'|V'|Q'|P(320)|pad] (biases folded)
__device__ float         g_agg  [(size_t)N_ * 256];
__device__ float         g_agg2 [(size_t)N_ * 256];
__device__ float         g_aggm [(size_t)N_ * 80];
__device__ __nv_bfloat16 g_aggm3[(size_t)N_ * 256];   // split of aggm (K0=80, pad 256)
__device__ float         g_nrm  [N_];
__device__ float         g_Wall [2 * 1152 * 256];     // fp32 [Wk;Wv;Wq;Wfused;0]
__device__ __nv_bfloat16 g_Wall3[2 * 1152 * 768];
__device__ float         g_bias1152[2 * 1152];        // [bk|bv|bq_eff|cb|0]
__device__ __nv_bfloat16 g_Win3 [256 * 768];
__device__ float         g_Wev  [2 * 256 * 80];
__device__ __nv_bfloat16 g_Wev3 [2 * 256 * 256];
__device__ __nv_bfloat16 g_Wout3[64 * 768];
__device__ float         g_b    [2 * 768];            // [bk|bv|bq_eff]

// ---------------- ptx helpers (family-safe, sm_80 baseline) ----------------
__device__ __forceinline__ uint32_t smem_u32(const void* p) {
    uint32_t a;
    asm("{ .reg .u64 t; cvta.to.shared.u64 t, %1; cvt.u32.u64 %0, t; }" : "=r"(a) : "l"(p));
    return a;
}
__device__ __forceinline__ void cp16(uint32_t dst, const void* src, int pred) {
    asm volatile(
        "{\n\t.reg .pred p;\n\t"
        "setp.ne.u32 p, %2, 0;\n\t"
        "@p cp.async.ca.shared.global [%0], [%1], 16;\n\t"
        "@!p cp.async.ca.shared.global [%0], [%1], 16, 0;\n\t}"
        :: "r"(dst), "l"(src), "r"(pred) : "memory");
}
__device__ __forceinline__ void cp_commit() {
    asm volatile("cp.async.commit_group;" ::: "memory");
}
__device__ __forceinline__ void ldm4(uint32_t* r, uint32_t addr) {
    asm volatile("ldmatrix.sync.aligned.m8n8.x4.shared.b16 {%0,%1,%2,%3}, [%4];"
                 : "=r"(r[0]), "=r"(r[1]), "=r"(r[2]), "=r"(r[3]) : "r"(addr));
}
__device__ __forceinline__ void ldm2(uint32_t* r, uint32_t addr) {
    asm volatile("ldmatrix.sync.aligned.m8n8.x2.shared.b16 {%0,%1}, [%2];"
                 : "=r"(r[0]), "=r"(r[1]) : "r"(addr));
}
__device__ __forceinline__ void mma16816(float* c, const uint32_t* a, const uint32_t* b) {
    asm volatile(
        "mma.sync.aligned.m16n8k16.row.col.f32.bf16.bf16.f32 "
        "{%0,%1,%2,%3},{%4,%5,%6,%7},{%8,%9},{%0,%1,%2,%3};"
        : "+f"(c[0]), "+f"(c[1]), "+f"(c[2]), "+f"(c[3])
        : "r"(a[0]), "r"(a[1]), "r"(a[2]), "r"(a[3]), "r"(b[0]), "r"(b[1]));
}

// ---------------- mma.sync GEMM: C(M x noutC) = A3(M x ka) @ W3(noutW x ka)^T ----------------
// 128x128 CTA tile, 8 warps (2M x 4N), K chunks of 64, cp.async double-buffered, dyn smem.
static constexpr int GSAS = 72;                 // padded smem stride (elems)
static constexpr int GSEG = 128 * GSAS;         // elems per (matrix, stage)
static constexpr int GSMEM_BYTES = 4 * GSEG * 2;  // 73728

template <bool GELU, bool SPLIT>
__global__ __launch_bounds__(256)
void mma_gemm(const __nv_bfloat16* __restrict__ A3, int ka,
              const __nv_bfloat16* __restrict__ W3, int noutW,
              const float* __restrict__ bias,
              float* __restrict__ C, int ldc, int M, int noutC,
              __nv_bfloat16* __restrict__ S3) {
    extern __shared__ __align__(16) __nv_bfloat16 smem[];
    int tid = threadIdx.x, lane = tid & 31, wid = tid >> 5;
    int wm = wid & 1, wn = wid >> 1;
    int bm = blockIdx.x * 128, bn = blockIdx.y * 128;
    int NC = ka >> 6;
    uint32_t sU = smem_u32(smem);

    int arow = (lane & 7) + ((lane >> 3) & 1) * 8;
    int acol = ((lane >> 4) & 1) * 8;
    int brow = lane & 7;
    int bk   = ((lane >> 3) & 1) * 8;

    float acc[4][4][4] = {};

#define LOADC(c, buf)                                                                    \
    {                                                                                    \
        int _c64 = (c) * 64;                                                             \
        uint32_t _ab = sU + (buf) * (2 * GSEG * 2);                                      \
        uint32_t _bb = _ab + GSEG * 2;                                                   \
        _Pragma("unroll")                                                                \
        for (int _k = 0; _k < 4; _k++) {                                                 \
            int _id = tid + _k * 256;                                                    \
            int _r = _id >> 3, _cg = (_id & 7) * 8;                                      \
            uint32_t _so = (uint32_t)(_r * GSAS + _cg) * 2;                              \
            int _gr = bm + _r; int _pa = _gr < M; int _ga = _pa ? _gr : 0;               \
            cp16(_ab + _so, A3 + (size_t)_ga * ka + _c64 + _cg, _pa);                    \
            int _wr = bn + _r; int _pb = _wr < noutW; int _wa = _pb ? _wr : 0;           \
            cp16(_bb + _so, W3 + (size_t)_wa * ka + _c64 + _cg, _pb);                    \
        }                                                                                \
        cp_commit();                                                                     \
    }

    LOADC(0, 0);
    for (int c = 0; c < NC; c++) {
        if (c + 1 < NC) {
            LOADC(c + 1, (c + 1) & 1);
            asm volatile("cp.async.wait_group 1;" ::: "memory");
        } else {
            asm volatile("cp.async.wait_group 0;" ::: "memory");
        }
        __syncthreads();
        uint32_t sAb = sU + (c & 1) * (2 * GSEG * 2);
        uint32_t sBb = sAb + GSEG * 2;
#pragma unroll
        for (int ks = 0; ks < 4; ks++) {
            uint32_t af[4][4];
#pragma unroll
            for (int mf = 0; mf < 4; mf++)
                ldm4(af[mf], sAb + (uint32_t)((wm * 64 + mf * 16 + arow) * GSAS + ks * 16 + acol) * 2);
            uint32_t bf[4][2];
#pragma unroll
            for (int nf = 0; nf < 4; nf++)
                ldm2(bf[nf], sBb + (uint32_t)((wn * 32 + nf * 8 + brow) * GSAS + ks * 16 + bk) * 2);
#pragma unroll
            for (int mf = 0; mf < 4; mf++)
#pragma unroll
                for (int nf = 0; nf < 4; nf++)
                    mma16816(acc[mf][nf], af[mf], bf[nf]);
        }
        __syncthreads();
    }
#undef LOADC

    // epilogue
    int cr = lane >> 2, cc = (lane & 3) * 2;
#pragma unroll
    for (int mf = 0; mf < 4; mf++) {
#pragma unroll
        for (int nf = 0; nf < 4; nf++) {
            int col = bn + wn * 32 + nf * 8 + cc;
            if (col >= noutC) continue;
            float bz0 = bias ? bias[col] : 0.f;
            float bz1 = bias ? bias[col + 1] : 0.f;
#pragma unroll
            for (int hh = 0; hh < 2; hh++) {
                int row = bm + wm * 64 + mf * 16 + cr + hh * 8;
                if (row >= M) continue;
                float v0 = acc[mf][nf][hh * 2 + 0] + bz0;
                float v1 = acc[mf][nf][hh * 2 + 1] + bz1;
                if (GELU) {
                    v0 = 0.5f * v0 * (1.0f + erff(v0 * 0.70710678118654752f));
                    v1 = 0.5f * v1 * (1.0f + erff(v1 * 0.70710678118654752f));
                }
                *reinterpret_cast<float2*>(C + (size_t)row * ldc + col) = make_float2(v0, v1);
                if (SPLIT) {
                    size_t b3 = (size_t)row * 3 * noutC;
                    __nv_bfloat16 h0 = __float2bfloat16(v0);
                    __nv_bfloat16 l0 = __float2bfloat16(v0 - __bfloat162float(h0));
                    __nv_bfloat16 h1 = __float2bfloat16(v1);
                    __nv_bfloat16 l1 = __float2bfloat16(v1 - __bfloat162float(h1));
                    S3[b3 + col] = h0; S3[b3 + col + 1] = h1;
                    S3[b3 + noutC + col] = l0; S3[b3 + noutC + col + 1] = l1;
                    S3[b3 + 2 * noutC + col] = h0; S3[b3 + 2 * noutC + col + 1] = h1;
                }
            }
        }
    }
}

// ---------------- pack / conversion ----------------
__global__ void pack_x3_kernel(const float* __restrict__ nf, const float* __restrict__ mem) {
    int idx = blockIdx.x * blockDim.x + threadIdx.x;
    int stride = gridDim.x * blockDim.x;
    for (int i = idx; i < N_ * 256; i += stride) {
        int n = i >> 8, j = i & 255;
        float v = (j < 128) ? nf[n * 128 + j] : mem[n * 128 + (j - 128)];
        __nv_bfloat16 hi = __float2bfloat16(v);
        __nv_bfloat16 lo = __float2bfloat16(v - __bfloat162float(hi));
        size_t b = (size_t)n * 768;
        g_X3[b + j] = hi; g_X3[b + 256 + j] = lo; g_X3[b + 512 + j] = hi;
    }
}

__global__ void pack_b_kernel(const float* __restrict__ wk_b, const float* __restrict__ wv_b,
                              const float* __restrict__ wq_b, const float* __restrict__ wq_w,
                              const float* __restrict__ te_phi) {
    int idx = blockIdx.x * blockDim.x + threadIdx.x;
    if (idx >= 2 * 768) return;
    int l = idx / 768, r = idx % 768;
    float v;
    if (r < 256)      v = wk_b[l * 256 + r];
    else if (r < 512) v = wv_b[l * 256 + (r - 256)];
    else {
        int rq = r - 512;
        v = wq_b[l * 256 + rq];
        for (int t = 0; t < 16; t++) {
            float ph = te_phi[l * 16 + t];
            float qt = (t == 0) ? ph : sinf(ph);
            v += wq_w[(size_t)(l * 256 + rq) * 272 + 256 + t] * qt;
        }
    }
    g_b[idx] = v;
}

__global__ void pack_wall_base_kernel(const float* __restrict__ wk_w, const float* __restrict__ wv_w,
                                      const float* __restrict__ wq_w) {
    int idx = blockIdx.x * blockDim.x + threadIdx.x;
    int stride = gridDim.x * blockDim.x;
    for (int i = idx; i < 2 * 1152 * 256; i += stride) {
        int l = i / (1152 * 256); int r = (i / 256) % 1152; int k = i & 255;
        if (r < 256)      g_Wall[i] = wk_w[(size_t)(l * 256 + r)       * 336 + k];
        else if (r < 512) g_Wall[i] = wv_w[(size_t)(l * 256 + (r-256)) * 336 + k];
        else if (r < 768) g_Wall[i] = wq_w[(size_t)(l * 256 + (r-512)) * 272 + k];
        else if (r >= 1088) g_Wall[i] = 0.f;
    }
    // biases: rows <768 copy g_b (pack_b ran earlier); rows >=1088 zero; 768..1087 by fused kernel
    for (int i = idx; i < 2 * 1152; i += stride) {
        int l = i / 1152, r = i % 1152;
        if (r < 768)       g_bias1152[i] = g_b[l * 768 + r];
        else if (r >= 1088) g_bias1152[i] = 0.f;
    }
    for (int i = idx; i < 2 * 256 * 80; i += stride) {
        int l = i / (256 * 80); int r = (i / 80) % 256; int p = i % 80;
        g_Wev[i] = wv_w[(size_t)(l * 256 + r) * 336 + 256 + p];
    }
}

// rows 768..1087 of W_all: (WeTk blockdiag) @ Wq_h, plus cb bias
__global__ __launch_bounds__(256)
void pack_wall_fused_kernel(const float* __restrict__ wk_w, const float* __restrict__ wq_w) {
    __shared__ float wk_s[64];
    int b = blockIdx.x;               // 0..639
    int l = b / 320, q = b % 320;
    int hd = q / 80, p = q % 80;
    int t = threadIdx.x;
    if (t < 64) wk_s[t] = wk_w[(size_t)(l * 256 + 64 * hd + t) * 336 + 256 + p];
    __syncthreads();
    float acc = 0.f;
    for (int c = 0; c < 64; c++)
        acc += wk_s[c] * wq_w[(size_t)(l * 256 + 64 * hd + c) * 272 + t];
    g_Wall[(size_t)l * 1152 * 256 + (size_t)(768 + q) * 256 + t] = acc;
    if (t == 0) {
        float cb = 0.f;
        for (int c = 0; c < 64; c++) cb += wk_s[c] * g_b[l * 768 + 512 + 64 * hd + c];
        g_bias1152[l * 1152 + 768 + q] = cb;
    }
}

// split fp32 (rows x K0) -> bf16 (rows x KA)
__global__ void conv_split_kernel(const float* __restrict__ src, int rows, int K0,
                                  __nv_bfloat16* __restrict__ dst, int KA, int actPat) {
    int idx = blockIdx.x * blockDim.x + threadIdx.x;
    int stride = gridDim.x * blockDim.x;
    long total = (long)rows * KA;
    for (long i = idx; i < total; i += stride) {
        int r = (int)(i / KA); int j = (int)(i % KA);
        __nv_bfloat16 o = __float2bfloat16(0.f);
        int blk = j / K0, jj = j % K0;
        if (blk < 3) {
            float v = src[(size_t)r * K0 + jj];
            __nv_bfloat16 hi = __float2bfloat16(v);
            if (blk == 0) o = hi;
            else {
                __nv_bfloat16 lo = __float2bfloat16(v - __bfloat162float(hi));
                if (actPat) o = (blk == 1) ? lo : hi;
                else        o = (blk == 1) ? hi : lo;
            }
        }
        dst[i] = o;
    }
}

__global__ void zero_agg_kernel() {
    int idx = blockIdx.x * blockDim.x + threadIdx.x;
    if (idx < N_ * 64) reinterpret_cast<float4*>(g_agg)[idx] = make_float4(0.f, 0.f, 0.f, 0.f);
    if (idx < N_ * 20) reinterpret_cast<float4*>(g_aggm)[idx] = make_float4(0.f, 0.f, 0.f, 0.f);
    if (idx < N_) g_nrm[idx] = 0.f;
}

// ---------------- edge attention + scatter (msg computed on the fly) ----------------
__device__ __forceinline__ void red_add4(float* p, float a, float b, float c, float d) {
    asm volatile("red.global.add.v4.f32 [%0], {%1, %2, %3, %4};"
                 :: "l"(p), "f"(a), "f"(b), "f"(c), "f"(d) : "memory");
}

__global__ __launch_bounds__(256)
void edge_attn_kernel(const int* __restrict__ src, const int* __restrict__ dst,
                      const float* __restrict__ ef, const float* __restrict__ et,
                      const float* __restrict__ te_w, const float* __restrict__ te_phi, int l) {
    int e = (blockIdx.x * blockDim.x + threadIdx.x) >> 5;
    int lane = threadIdx.x & 31;
    if (e >= E_) return;
    int s = src[e], d = dst[e];
    int jn = dst[d];                       // faithful h_dst[dst] quirk
    size_t sb = (size_t)s  * 1152;
    size_t jb = (size_t)jn * 1152;
    int o = lane * 8;
    int head = lane >> 3, hl = lane & 7;

    // time encoding (lanes 0..15 hold tenc[lane])
    float tv = 0.f;
    {
        float te = et[e];
        if (lane < 16) {
            float wt = -te * te_w[l * 16 + lane] + te_phi[l * 16 + lane];
            tv = (lane == 0) ? wt : sinf(wt);
        }
    }

    // node QK part (biases already folded into K', Q')
    float acc = 0.f;
#pragma unroll
    for (int i = 0; i < 8; i += 4) {
        float4 hk = *reinterpret_cast<const float4*>(g_hkvqp + sb + o + i);
        float4 hq = *reinterpret_cast<const float4*>(g_hkvqp + jb + 512 + o + i);
        acc += hk.x * hq.x + hk.y * hq.y + hk.z * hq.z + hk.w * hq.w;
    }
    // edge-K part: P[jn,head,:] . [ef | tenc]
    {
        const float* Pr  = g_hkvqp + jb + 768 + head * 80 + hl;
        const float* efp = ef + (size_t)e * 64 + hl;
#pragma unroll
        for (int t = 0; t < 8; t++) acc += Pr[8 * t] * efp[8 * t];
        float t8 = __shfl_sync(0xffffffffu, tv, hl);
        float t9 = __shfl_sync(0xffffffffu, tv, hl + 8);
        acc += Pr[64] * t8 + Pr[72] * t9;
    }
    acc += __shfl_xor_sync(0xffffffffu, acc, 1);
    acc += __shfl_xor_sync(0xffffffffu, acc, 2);
    acc += __shfl_xor_sync(0xffffffffu, acc, 4);
    float sc = fminf(5.0f, fmaxf(-5.0f, acc * 0.125f));
    float a = __expf(sc);
    float sm = a;
    sm += __shfl_xor_sync(0xffffffffu, sm, 8);
    sm += __shfl_xor_sync(0xffffffffu, sm, 16);
    float af = sm * 0.25f;

    // scatter: agg += af * V'[s]   (bias folded)
    float v[8];
#pragma unroll
    for (int i = 0; i < 8; i += 4) {
        float4 hv = *reinterpret_cast<const float4*>(g_hkvqp + sb + 256 + o + i);
        v[i + 0] = hv.x * af; v[i + 1] = hv.y * af;
        v[i + 2] = hv.z * af; v[i + 3] = hv.w * af;
    }
    float* ag = g_agg + (size_t)d * 256 + o;
    red_add4(ag,     v[0], v[1], v[2], v[3]);
    red_add4(ag + 4, v[4], v[5], v[6], v[7]);

    // scatter: aggm += af * [ef | tenc] (lanes 0..19)
    int bidx = (lane >= 16 && lane < 20) ? (lane - 16) * 4 : 0;
    float s0 = __shfl_sync(0xffffffffu, tv, bidx);
    float s1 = __shfl_sync(0xffffffffu, tv, bidx + 1);
    float s2 = __shfl_sync(0xffffffffu, tv, bidx + 2);
    float s3 = __shfl_sync(0xffffffffu, tv, bidx + 3);
    if (lane < 20) {
        float4 m4;
        if (lane < 16) m4 = *reinterpret_cast<const float4*>(ef + (size_t)e * 64 + lane * 4);
        else           m4 = make_float4(s0, s1, s2, s3);
        red_add4(g_aggm + (size_t)d * 80 + lane * 4, m4.x * af, m4.y * af, m4.z * af, m4.w * af);
    }
    if (lane == 0) atomicAdd(g_nrm + d, af);
}

// ---------------- node update: h = LN(h + LN((agg+agg2)/(nrm+eps))); writes h and h3 ----------------
__global__ __launch_bounds__(256)
void node_update_kernel(const float* __restrict__ aw, const float* __restrict__ ab,
                        const float* __restrict__ lw, const float* __restrict__ lb) {
    int n = (blockIdx.x * blockDim.x + threadIdx.x) >> 5;
    int lane = threadIdx.x & 31;
    if (n >= N_) return;
    size_t base = (size_t)n * 256;
    int o = lane * 8;
    float inv = 1.0f / (g_nrm[n] + 1e-8f);
    float x[8];
    {
        float4 a0 = *reinterpret_cast<const float4*>(g_agg  + base + o);
        float4 a1 = *reinterpret_cast<const float4*>(g_agg  + base + o + 4);
        float4 b0 = *reinterpret_cast<const float4*>(g_agg2 + base + o);
        float4 b1 = *reinterpret_cast<const float4*>(g_agg2 + base + o + 4);
        x[0] = (a0.x + b0.x) * inv; x[1] = (a0.y + b0.y) * inv;
        x[2] = (a0.z + b0.z) * inv; x[3] = (a0.w + b0.w) * inv;
        x[4] = (a1.x + b1.x) * inv; x[5] = (a1.y + b1.y) * inv;
        x[6] = (a1.z + b1.z) * inv; x[7] = (a1.w + b1.w) * inv;
    }
    float s = 0.f;
#pragma unroll
    for (int i = 0; i < 8; i++) s += x[i];
#pragma unroll
    for (int m = 16; m >= 1; m >>= 1) s += __shfl_xor_sync(0xffffffffu, s, m);
    float mean = s * (1.0f / 256.0f);
    float vv = 0.f;
#pragma unroll
    for (int i = 0; i < 8; i++) { float dx = x[i] - mean; vv += dx * dx; }
#pragma unroll
    for (int m = 16; m >= 1; m >>= 1) vv += __shfl_xor_sync(0xffffffffu, vv, m);
    float is = rsqrtf(vv * (1.0f / 256.0f) + 1e-5f);
    float r[8];
#pragma unroll
    for (int i = 0; i < 8; i++) {
        float hn = (x[i] - mean) * is * aw[o + i] + ab[o + i];
        r[i] = g_h[base + o + i] + hn;
    }
    float s2 = 0.f;
#pragma unroll
    for (int i = 0; i < 8; i++) s2 += r[i];
#pragma unroll
    for (int m = 16; m >= 1; m >>= 1) s2 += __shfl_xor_sync(0xffffffffu, s2, m);
    float mean2 = s2 * (1.0f / 256.0f);
    float v2 = 0.f;
#pragma unroll
    for (int i = 0; i < 8; i++) { float dx = r[i] - mean2; v2 += dx * dx; }
#pragma unroll
    for (int m = 16; m >= 1; m >>= 1) v2 += __shfl_xor_sync(0xffffffffu, v2, m);
    float is2 = rsqrtf(v2 * (1.0f / 256.0f) + 1e-5f);
    size_t b3 = (size_t)n * 768;
#pragma unroll
    for (int i = 0; i < 8; i++) {
        float hv = (r[i] - mean2) * is2 * lw[o + i] + lb[o + i];
        g_h[base + o + i] = hv;
        __nv_bfloat16 hi = __float2bfloat16(hv);
        __nv_bfloat16 lo = __float2bfloat16(hv - __bfloat162float(hi));
        g_h3[b3 + o + i] = hi;
        g_h3[b3 + 256 + o + i] = lo;
        g_h3[b3 + 512 + o + i] = hi;
    }
}

// ---------------- launch ----------------
extern "C" void kernel_launch(void* const* d_in, const int* in_sizes, int n_in,
                              void* d_out, int out_size) {
    const float* node_feat  = (const float*)d_in[0];
    const float* memory     = (const float*)d_in[1];
    const int*   eidx       = (const int*)  d_in[2];
    const float* edge_feat  = (const float*)d_in[3];
    const float* edge_times = (const float*)d_in[4];
    const float* in_w       = (const float*)d_in[5];
    const float* in_b       = (const float*)d_in[6];
    const float* te_w       = (const float*)d_in[7];
    const float* te_phi     = (const float*)d_in[8];
    const float* wq_w       = (const float*)d_in[9];
    const float* wq_b       = (const float*)d_in[10];
    const float* wk_w       = (const float*)d_in[11];
    const float* wk_b       = (const float*)d_in[12];
    const float* wv_w       = (const float*)d_in[13];
    const float* wv_b       = (const float*)d_in[14];
    const float* attn_ln_w  = (const float*)d_in[15];
    const float* attn_ln_b  = (const float*)d_in[16];
    const float* ln_w       = (const float*)d_in[17];
    const float* ln_b       = (const float*)d_in[18];
    const float* out_w      = (const float*)d_in[19];
    const float* out_b      = (const float*)d_in[20];
    const int* src = eidx;
    const int* dst = eidx + E_;
    float* out = (float*)d_out;

    float *ph, *phkvqp, *pAggm, *pAgg2, *pWall, *pWev, *pBias;
    __nv_bfloat16 *pX3, *ph3, *pAggm3, *pWall3, *pWin3, *pWev3, *pWout3;
    cudaGetSymbolAddress((void**)&ph,     g_h);
    cudaGetSymbolAddress((void**)&phkvqp, g_hkvqp);
    cudaGetSymbolAddress((void**)&pAggm,  g_aggm);
    cudaGetSymbolAddress((void**)&pAgg2,  g_agg2);
    cudaGetSymbolAddress((void**)&pWall,  g_Wall);
    cudaGetSymbolAddress((void**)&pWev,   g_Wev);
    cudaGetSymbolAddress((void**)&pBias,  g_bias1152);
    cudaGetSymbolAddress((void**)&pX3,    g_X3);
    cudaGetSymbolAddress((void**)&ph3,    g_h3);
    cudaGetSymbolAddress((void**)&pAggm3, g_aggm3);
    cudaGetSymbolAddress((void**)&pWall3, g_Wall3);
    cudaGetSymbolAddress((void**)&pWin3,  g_Win3);
    cudaGetSymbolAddress((void**)&pWev3,  g_Wev3);
    cudaGetSymbolAddress((void**)&pWout3, g_Wout3);

    cudaFuncSetAttribute(mma_gemm<false, true>,  cudaFuncAttributeMaxDynamicSharedMemorySize, GSMEM_BYTES);
    cudaFuncSetAttribute(mma_gemm<false, false>, cudaFuncAttributeMaxDynamicSharedMemorySize, GSMEM_BYTES);
    cudaFuncSetAttribute(mma_gemm<true, false>,  cudaFuncAttributeMaxDynamicSharedMemorySize, GSMEM_BYTES);

    const int GX = (N_ + 127) / 128;  // 391

    pack_x3_kernel<<<4096, 256>>>(node_feat, memory);
    pack_b_kernel<<<6, 256>>>(wk_b, wv_b, wq_b, wq_w, te_phi);
    pack_wall_base_kernel<<<2304, 256>>>(wk_w, wv_w, wq_w);
    pack_wall_fused_kernel<<<640, 256>>>(wk_w, wq_w);
    conv_split_kernel<<<4096, 256>>>(pWall, 2 * 1152, 256, pWall3, 768, 0);
    conv_split_kernel<<<768, 256>>>((const float*)in_w, 256, 256, pWin3, 768, 0);
    conv_split_kernel<<<192, 256>>>((const float*)out_w, 64, 256, pWout3, 768, 0);
    conv_split_kernel<<<512, 256>>>(pWev, 2 * 256, 80, pWev3, 256, 0);

    // h = X @ in_w^T + in_b (also emits h3 split)
    mma_gemm<false, true><<<dim3(GX, 2), 256, GSMEM_BYTES>>>(pX3, 768, pWin3, 256, in_b,
                                                             ph, 256, N_, 256, ph3);

    for (int l = 0; l < 2; l++) {
        // [K'|V'|Q'|P] = h @ W_all^T + [bk|bv|bq_eff|cb]
        mma_gemm<false, false><<<dim3(GX, 9), 256, GSMEM_BYTES>>>(
            ph3, 768, pWall3 + (size_t)l * 1152 * 768, 1152,
            pBias + l * 1152, phkvqp, 1152, N_, 1088, nullptr);
        zero_agg_kernel<<<12500, 256>>>();
        edge_attn_kernel<<<25000, 256>>>(src, dst, edge_feat, edge_times, te_w, te_phi, l);
        conv_split_kernel<<<4096, 256>>>(pAggm, N_, 80, pAggm3, 256, 1);
        // agg2 = aggm @ We_v^T
        mma_gemm<false, false><<<dim3(GX, 2), 256, GSMEM_BYTES>>>(
            pAggm3, 256, pWev3 + (size_t)l * 256 * 256, 256,
            nullptr, pAgg2, 256, N_, 256, nullptr);
        node_update_kernel<<<6250, 256>>>(attn_ln_w + l * 256, attn_ln_b + l * 256,
                                          ln_w + l * 256, ln_b + l * 256);
    }

    // out = gelu(h @ out_w^T + out_b)
    mma_gemm<true, false><<<dim3(GX, 1), 256, GSMEM_BYTES>>>(ph3, 768, pWout3, 64, out_b,
                                                             out, 64, N_, 64, nullptr);
}